// round 1
// baseline (speedup 1.0000x reference)
#include <cuda_runtime.h>
#include <cstdint>

#define N_TOK   131072
#define DIM     64
#define NE      1024
#define DECAYF  0.99f
#define ONE_M_D 0.01f
#define EPSF    1e-5f

// ---- output layout (reference return order, flattened, float32) ----
#define O_Q     0                       // quantize_st: N_TOK*DIM
#define O_DIFF  (O_Q + N_TOK*DIM)       // scalar
#define O_IND   (O_DIFF + 1)            // N_TOK
#define O_NEMB  (O_IND + N_TOK)         // DIM*NE
#define O_NCS   (O_NEMB + DIM*NE)       // NE
#define O_NEA   (O_NCS + NE)            // DIM*NE

// ---- scratch (no allocations allowed -> device globals) ----
__device__ float  g_enorm[NE];
__device__ float  g_embedT[NE*DIM];     // embed transposed: row j = codeword j (contiguous 64 floats)
__device__ float  g_count[NE];
__device__ float  g_embed_sum[DIM*NE];
__device__ double g_diff_acc;

// ---- f32x2 packed helpers (sm_103a) ----
__device__ __forceinline__ unsigned long long pack2(float v) {
    unsigned long long r;
    asm("mov.b64 %0, {%1, %1};" : "=l"(r) : "f"(v));
    return r;
}
__device__ __forceinline__ void fma2(unsigned long long& d, unsigned long long a, unsigned long long b) {
    asm("fma.rn.f32x2 %0, %1, %2, %0;" : "+l"(d) : "l"(a), "l"(b));
}
__device__ __forceinline__ void unpack2(unsigned long long v, float& lo, float& hi) {
    asm("mov.b64 {%0, %1}, %2;" : "=f"(lo), "=f"(hi) : "l"(v));
}

// =====================================================================
// K0: zero scratch, compute ||e_j||^2, build transposed codebook
// =====================================================================
__global__ void vq_prep(const float* __restrict__ embed) {
    int j = blockIdx.x * blockDim.x + threadIdx.x;   // 4 x 256 = 1024
    if (j < NE) {
        float s = 0.f;
        #pragma unroll 8
        for (int d = 0; d < DIM; ++d) {
            float v = embed[d * NE + j];
            g_embedT[j * DIM + d] = v;
            s += v * v;
        }
        g_enorm[j] = s;
        g_count[j] = 0.f;
    }
    for (int i = j; i < DIM * NE; i += NE) g_embed_sum[i] = 0.f;
    if (j == 0) g_diff_acc = 0.0;
}

// =====================================================================
// K1: distance GEMM + argmin + quantize gather + diff + segment atomics
//   block tile: 128 tokens x 128 codes per chunk (8 chunks), K=64 resident
//   thread micro-tile: 8 rows x 8 cols, packed f32x2 over column pairs
// =====================================================================
#define XS_STRIDE 132
#define SMEM_FLOATS (64*XS_STRIDE + 64*128)

__global__ void __launch_bounds__(256, 2) vq_main(const float* __restrict__ x,
                                                  const float* __restrict__ embed,
                                                  float* __restrict__ out) {
    extern __shared__ float sm[];
    float* xs = sm;                     // [64][132]  xs[k*132 + m]
    float* es = sm + 64 * XS_STRIDE;    // [64][128]  es[k*128 + j]

    const int tid = threadIdx.x;
    const int bm  = blockIdx.x * 128;   // token base
    const int jg  = tid & 15;           // column group (8 cols)
    const int mg  = tid >> 4;           // row group (8 rows)

    // ---- load x tile, transposed into xs[k][m] ----
    #pragma unroll
    for (int p = 0; p < 8; ++p) {
        int f  = tid + p * 256;         // 2048 float4s
        int m  = f >> 4;
        int k4 = f & 15;
        float4 v = *(const float4*)(x + (size_t)(bm + m) * DIM + k4 * 4);
        xs[(k4*4 + 0) * XS_STRIDE + m] = v.x;
        xs[(k4*4 + 1) * XS_STRIDE + m] = v.y;
        xs[(k4*4 + 2) * XS_STRIDE + m] = v.z;
        xs[(k4*4 + 3) * XS_STRIDE + m] = v.w;
    }

    float rmin[8];
    int   ridx[8];
    #pragma unroll
    for (int i = 0; i < 8; ++i) { rmin[i] = 3.402823466e+38f; ridx[i] = 0; }

    for (int c = 0; c < 8; ++c) {
        __syncthreads();   // prev chunk consumers done (first iter: covers xs stores too)
        // ---- load codebook chunk es[k][j] ----
        #pragma unroll
        for (int p = 0; p < 8; ++p) {
            int f  = tid + p * 256;
            int k  = f >> 5;
            int c4 = f & 31;
            *(float4*)(es + k * 128 + c4 * 4) =
                *(const float4*)(embed + (size_t)k * NE + c * 128 + c4 * 4);
        }
        __syncthreads();

        unsigned long long acc[8][4];
        #pragma unroll
        for (int i = 0; i < 8; ++i)
            #pragma unroll
            for (int jj = 0; jj < 4; ++jj) acc[i][jj] = 0ULL;

        const float* xbase = xs + mg * 8;
        const float* ebase = es + jg * 8;

        #pragma unroll 8
        for (int k = 0; k < 64; ++k) {
            float4 av0 = *(const float4*)(xbase + k * XS_STRIDE);
            float4 av1 = *(const float4*)(xbase + k * XS_STRIDE + 4);
            unsigned long long a2[8];
            a2[0] = pack2(av0.x); a2[1] = pack2(av0.y);
            a2[2] = pack2(av0.z); a2[3] = pack2(av0.w);
            a2[4] = pack2(av1.x); a2[5] = pack2(av1.y);
            a2[6] = pack2(av1.z); a2[7] = pack2(av1.w);
            unsigned long long b2[4];
            #pragma unroll
            for (int jj = 0; jj < 4; ++jj)
                b2[jj] = *(const unsigned long long*)(ebase + k * 128 + 2 * jj);
            #pragma unroll
            for (int i = 0; i < 8; ++i)
                #pragma unroll
                for (int jj = 0; jj < 4; ++jj)
                    fma2(acc[i][jj], a2[i], b2[jj]);
        }

        // ---- dist = enorm - 2*dot ; track running argmin ----
        float en[8];
        const float* enp = g_enorm + c * 128 + jg * 8;
        #pragma unroll
        for (int u = 0; u < 8; ++u) en[u] = enp[u];

        #pragma unroll
        for (int i = 0; i < 8; ++i) {
            #pragma unroll
            for (int jj = 0; jj < 4; ++jj) {
                float lo, hi;
                unpack2(acc[i][jj], lo, hi);
                int j0 = c * 128 + jg * 8 + 2 * jj;
                float d0 = fmaf(-2.f, lo, en[2*jj]);
                float d1 = fmaf(-2.f, hi, en[2*jj + 1]);
                if (d0 < rmin[i]) { rmin[i] = d0; ridx[i] = j0; }
                if (d1 < rmin[i]) { rmin[i] = d1; ridx[i] = j0 + 1; }
            }
        }
    }

    // ---- cross-thread argmin reduction (reuse es region) ----
    __syncthreads();
    float* rmin_s = es;                         // [128][16]
    int*   ridx_s = (int*)(es + 128 * 16);      // [128][16]
    #pragma unroll
    for (int i = 0; i < 8; ++i) {
        int r = mg * 8 + i;
        rmin_s[r * 16 + jg] = rmin[i];
        ridx_s[r * 16 + jg] = ridx[i];
    }
    __syncthreads();

    __shared__ int s_ind[128];
    if (tid < 128) {
        float bv = rmin_s[tid * 16];
        int   bi = ridx_s[tid * 16];
        #pragma unroll
        for (int t = 1; t < 16; ++t) {
            float v = rmin_s[tid * 16 + t];
            int   ix = ridx_s[tid * 16 + t];
            if (v < bv || (v == bv && ix < bi)) { bv = v; bi = ix; }
        }
        s_ind[tid] = bi;
        out[O_IND + bm + tid] = (float)bi;
        atomicAdd(&g_count[bi], 1.0f);
    }
    __syncthreads();

    // ---- epilogue: 2 threads per token (32 dims each) ----
    const int tk   = tid >> 1;
    const int half = tid & 1;
    const int ind  = s_ind[tk];
    const int token = bm + tk;
    const float* qrow = g_embedT + (size_t)ind * DIM + half * 32;
    float dsum = 0.f;
    #pragma unroll
    for (int u = 0; u < 32; u += 4) {
        float4 q = *(const float4*)(qrow + u);
        int kb = half * 32 + u;
        float x0 = xs[(kb + 0) * XS_STRIDE + tk];
        float x1 = xs[(kb + 1) * XS_STRIDE + tk];
        float x2 = xs[(kb + 2) * XS_STRIDE + tk];
        float x3 = xs[(kb + 3) * XS_STRIDE + tk];
        float e0 = q.x - x0, e1 = q.y - x1, e2 = q.z - x2, e3 = q.w - x3;
        dsum += e0*e0 + e1*e1 + e2*e2 + e3*e3;
        *(float4*)(out + O_Q + (size_t)token * DIM + kb) = q;
        atomicAdd(&g_embed_sum[(kb + 0) * NE + ind], x0);
        atomicAdd(&g_embed_sum[(kb + 1) * NE + ind], x1);
        atomicAdd(&g_embed_sum[(kb + 2) * NE + ind], x2);
        atomicAdd(&g_embed_sum[(kb + 3) * NE + ind], x3);
    }

    // ---- block-reduce diff, single double atomic per block ----
    #pragma unroll
    for (int off = 16; off > 0; off >>= 1)
        dsum += __shfl_xor_sync(0xFFFFFFFFu, dsum, off);
    __shared__ float s_red[8];
    if ((tid & 31) == 0) s_red[tid >> 5] = dsum;
    __syncthreads();
    if (tid == 0) {
        float t = 0.f;
        #pragma unroll
        for (int w = 0; w < 8; ++w) t += s_red[w];
        atomicAdd(&g_diff_acc, (double)t);
    }
}

// =====================================================================
// K2: EMA finalize (single block, 1024 threads)
// =====================================================================
__global__ void vq_finalize(const float* __restrict__ cluster_size,
                            const float* __restrict__ embed_avg,
                            float* __restrict__ out) {
    __shared__ float sr[NE];
    int j = threadIdx.x;
    float ncs = cluster_size[j] * DECAYF + ONE_M_D * g_count[j];
    out[O_NCS + j] = ncs;
    sr[j] = ncs;
    __syncthreads();
    for (int s = 512; s > 0; s >>= 1) {
        if (j < s) sr[j] += sr[j + s];
        __syncthreads();
    }
    float n = sr[0];
    float csn = (ncs + EPSF) / (n + (float)(NE * 1e-5)) * n;
    #pragma unroll 8
    for (int d = 0; d < DIM; ++d) {
        int idx = d * NE + j;
        float nea = embed_avg[idx] * DECAYF + ONE_M_D * g_embed_sum[idx];
        out[O_NEA + idx]  = nea;
        out[O_NEMB + idx] = nea / csn;
    }
    if (j == 0) out[O_DIFF] = (float)(g_diff_acc * (1.0 / (double)(N_TOK * DIM)));
}

extern "C" void kernel_launch(void* const* d_in, const int* in_sizes, int n_in,
                              void* d_out, int out_size) {
    const float* x            = (const float*)d_in[0];
    const float* embed        = (const float*)d_in[1];
    const float* cluster_size = (const float*)d_in[2];
    const float* embed_avg    = (const float*)d_in[3];
    float* out = (float*)d_out;

    cudaFuncSetAttribute(vq_main, cudaFuncAttributeMaxDynamicSharedMemorySize,
                         SMEM_FLOATS * (int)sizeof(float));

    vq_prep<<<4, 256>>>(embed);
    vq_main<<<N_TOK / 128, 256, SMEM_FLOATS * sizeof(float)>>>(x, embed, out);
    vq_finalize<<<1, NE>>>(cluster_size, embed_avg, out);
}